// round 1
// baseline (speedup 1.0000x reference)
#include <cuda_runtime.h>
#include <math.h>

// Problem constants
#define BB 32
#define NN 4096
#define DD 512
#define CC 64
#define RTOT (BB*NN)          // 131072 rows
#define MT 32                 // rows per GEMM tile
#define NTILES (RTOT/MT)      // 4096
#define XP 520                // x_s row pitch (pad vs 512 to dodge bank conflicts)
#define AP 68                 // a_s row pitch (pad vs 64, keeps float4 16B-aligned)
#define CHUNK 128             // rows per feature-partial block
#define NCHUNK (NN/CHUNK)     // 32

// Device scratch (allocation-free rule: __device__ globals)
__device__ float g_sw[(size_t)RTOT*CC];       // score * invnorm * valid, 32 MiB
__device__ int   g_counts[BB*CC];
__device__ int   g_index[BB];
__device__ float g_part[(size_t)BB*NCHUNK*DD];

// mask may be int64 (jax x64 on) or int32 (x64 off). Values are in [1, 4096],
// so if stored as little-endian int64, word 1 (high half of element 0) is 0.
__device__ __forceinline__ int decode_mask(const int* mr, int b) {
    return (mr[1] == 0) ? mr[2*b] : mr[b];
}

__global__ void zero_counts_kernel() {
    int i = blockIdx.x*blockDim.x + threadIdx.x;
    if (i < BB*CC) g_counts[i] = 0;
}

__global__ __launch_bounds__(256, 1)
void main_kernel(const float* __restrict__ x, const int* __restrict__ maskr,
                 const float* __restrict__ anchors) {
    extern __shared__ float sm[];
    float* a_s    = sm;                    // [DD][AP]  anchors transposed (k-major)
    float* x_s    = a_s + DD*AP;           // [MT][XP]  x tile row-major, padded
    float* dots_s = x_s + MT*XP;           // [MT][CC]
    float* anorm_s= dots_s + MT*CC;        // [CC]
    float* norm_s = anorm_s + CC;          // [MT]
    int*   mask_s = (int*)(norm_s + MT);   // [BB]

    const int tid  = threadIdx.x;
    const int lane = tid & 31, warp = tid >> 5;

    // Load anchors once per block (transposed into a_s[k][c])
    for (int i = tid; i < CC*DD; i += 256) {
        int c = i >> 9;          // i / 512
        int k = i & (DD-1);
        a_s[k*AP + c] = anchors[i];
    }
    if (tid < BB) mask_s[tid] = decode_mask(maskr, tid);
    __syncthreads();
    if (tid < CC) {
        float s = 0.f;
        for (int k = 0; k < DD; k++) { float v = a_s[k*AP + tid]; s = fmaf(v, v, s); }
        anorm_s[tid] = s;
    }
    __syncthreads();

    const int tx = tid & 15, ty = tid >> 4;
    const int m0 = ty*2, c0 = tx*4;

    for (int tile = blockIdx.x; tile < NTILES; tile += gridDim.x) {
        const int rowbase = tile*MT;
        const int b     = rowbase >> 12;        // N = 4096
        const int nbase = rowbase & (NN-1);
        if (nbase >= mask_s[b]) continue;       // fully-invalid tile: skip (uniform)

        // ---- load x tile (32 x 512 fp32), coalesced float4 ----
        const float4* xg = (const float4*)(x + (size_t)rowbase*DD);
        #pragma unroll
        for (int j = 0; j < 16; j++) {
            int idx = tid + j*256;              // float4 index within tile
            int r = idx >> 7, k4 = idx & 127;
            float4 v = xg[idx];
            float* p = &x_s[r*XP + k4*4];
            p[0]=v.x; p[1]=v.y; p[2]=v.z; p[3]=v.w;
        }
        __syncthreads();

        // ---- row norms (warp per row, strided, conflict-free with pad) ----
        for (int m = warp; m < MT; m += 8) {
            float s = 0.f;
            for (int k = lane; k < DD; k += 32) { float v = x_s[m*XP + k]; s = fmaf(v, v, s); }
            #pragma unroll
            for (int o = 16; o; o >>= 1) s += __shfl_xor_sync(0xffffffffu, s, o);
            if (lane == 0) norm_s[m] = s;
        }

        // ---- GEMM: 32x64 tile, thread tile 2x4 ----
        float acc00=0,acc01=0,acc02=0,acc03=0,acc10=0,acc11=0,acc12=0,acc13=0;
        const float* xr0 = x_s + m0*XP;
        const float* xr1 = x_s + (m0+1)*XP;
        #pragma unroll 4
        for (int k = 0; k < DD; k++) {
            float xv0 = xr0[k], xv1 = xr1[k];
            float4 a = *reinterpret_cast<const float4*>(a_s + k*AP + c0);
            acc00 = fmaf(xv0, a.x, acc00); acc01 = fmaf(xv0, a.y, acc01);
            acc02 = fmaf(xv0, a.z, acc02); acc03 = fmaf(xv0, a.w, acc03);
            acc10 = fmaf(xv1, a.x, acc10); acc11 = fmaf(xv1, a.y, acc11);
            acc12 = fmaf(xv1, a.z, acc12); acc13 = fmaf(xv1, a.w, acc13);
        }
        dots_s[m0*CC + c0+0] = acc00; dots_s[m0*CC + c0+1] = acc01;
        dots_s[m0*CC + c0+2] = acc02; dots_s[m0*CC + c0+3] = acc03;
        dots_s[(m0+1)*CC + c0+0] = acc10; dots_s[(m0+1)*CC + c0+1] = acc11;
        dots_s[(m0+1)*CC + c0+2] = acc12; dots_s[(m0+1)*CC + c0+3] = acc13;
        __syncthreads();

        // ---- per-row epilogue: dist -> softmax(1/dist) -> store, argmin, counts ----
        for (int m = warp; m < MT; m += 8) {
            const int row = rowbase + m;
            const int n = row & (NN-1);
            const bool valid = n < mask_s[b];
            const float n2  = norm_s[m];
            const float inv = 1.f / fmaxf(sqrtf(n2), 1e-12f);
            const float sxn2 = n2 * inv * inv;     // sum(xn^2), matches reference
            const int cA = lane, cB = lane + 32;
            const float dA = dots_s[m*CC + cA], dB = dots_s[m*CC + cB];
            const float sqA = sxn2 + anorm_s[cA] - 2.f*dA*inv;
            const float sqB = sxn2 + anorm_s[cB] - 2.f*dB*inv;
            const float idA = 1.f / sqrtf(fmaxf(sqA, 0.f));
            const float idB = 1.f / sqrtf(fmaxf(sqB, 0.f));
            // softmax over 64 (2 per lane)
            float mx = fmaxf(idA, idB);
            #pragma unroll
            for (int o = 16; o; o >>= 1) mx = fmaxf(mx, __shfl_xor_sync(0xffffffffu, mx, o));
            const float eA = expf(idA - mx), eB = expf(idB - mx);
            float ss = eA + eB;
            #pragma unroll
            for (int o = 16; o; o >>= 1) ss += __shfl_xor_sync(0xffffffffu, ss, o);
            const float rs = 1.f / ss;
            const size_t base = (size_t)row * CC;
            g_sw[base + cA] = valid ? eA*rs*inv : 0.f;
            g_sw[base + cB] = valid ? eB*rs*inv : 0.f;
            // argmax score == argmax invd; ties -> lower index (jnp.argmax semantics)
            float bv; int bi;
            if (idB > idA) { bv = idB; bi = cB; } else { bv = idA; bi = cA; }
            #pragma unroll
            for (int o = 16; o; o >>= 1) {
                float ov = __shfl_xor_sync(0xffffffffu, bv, o);
                int   oi = __shfl_xor_sync(0xffffffffu, bi, o);
                if (ov > bv || (ov == bv && oi < bi)) { bv = ov; bi = oi; }
            }
            if (lane == 0 && valid) atomicAdd(&g_counts[b*CC + bi], 1);
        }
        __syncthreads();
    }
}

__global__ void index_kernel() {
    __shared__ int sv[CC], si[CC];
    const int b = blockIdx.x, c = threadIdx.x;
    sv[c] = g_counts[b*CC + c]; si[c] = c;
    __syncthreads();
    for (int o = 32; o; o >>= 1) {
        if (c < o) {
            if (sv[c+o] > sv[c] || (sv[c+o] == sv[c] && si[c+o] < si[c])) {
                sv[c] = sv[c+o]; si[c] = si[c+o];
            }
        }
        __syncthreads();
    }
    if (c == 0) g_index[b] = si[0];
}

__global__ __launch_bounds__(256)
void feat_part_kernel(const float* __restrict__ x, const int* __restrict__ maskr) {
    const int b = blockIdx.y, ch = blockIdx.x;
    const int tid = threadIdx.x;
    __shared__ float w_s[CHUNK];
    __shared__ int s_idx, s_nv;
    if (tid == 0) {
        s_idx = g_index[b];
        int nv = decode_mask(maskr, b) - ch*CHUNK;
        s_nv = nv < 0 ? 0 : (nv > CHUNK ? CHUNK : nv);
    }
    __syncthreads();
    const int idx = s_idx, nv = s_nv;
    const int rowbase = b*NN + ch*CHUNK;
    if (tid < CHUNK) w_s[tid] = (tid < nv) ? g_sw[(size_t)(rowbase + tid)*CC + idx] : 0.f;
    __syncthreads();
    float a0 = 0.f, a1 = 0.f;
    const float* xb = x + (size_t)rowbase*DD;
    #pragma unroll 4
    for (int r = 0; r < nv; r++) {
        const float w = w_s[r];
        a0 = fmaf(xb[(size_t)r*DD + tid],       w, a0);
        a1 = fmaf(xb[(size_t)r*DD + tid + 256], w, a1);
    }
    float* gp = g_part + ((size_t)b*NCHUNK + ch)*DD;
    gp[tid] = a0; gp[tid + 256] = a1;
}

__global__ void feat_reduce_kernel(float* __restrict__ out) {
    const int i = blockIdx.x*blockDim.x + threadIdx.x;  // BB*DD = 16384
    const int b = i >> 9, d = i & (DD-1);
    float s = 0.f;
    #pragma unroll
    for (int ch = 0; ch < NCHUNK; ch++) s += g_part[((size_t)b*NCHUNK + ch)*DD + d];
    out[i] = s;
}

extern "C" void kernel_launch(void* const* d_in, const int* in_sizes, int n_in,
                              void* d_out, int out_size) {
    const float* x       = (const float*)d_in[0];
    const int*   mask    = (const int*)d_in[1];
    const float* anchors = (const float*)d_in[2];
    float* out = (float*)d_out;

    const size_t smem = (size_t)(DD*AP + MT*XP + MT*CC + CC + MT)*sizeof(float)
                      + BB*sizeof(int);   // ~209.5 KB
    cudaFuncSetAttribute(main_kernel, cudaFuncAttributeMaxDynamicSharedMemorySize, (int)smem);

    zero_counts_kernel<<<8, 256>>>();
    main_kernel<<<152, 256, smem>>>(x, mask, anchors);
    index_kernel<<<BB, CC>>>();
    dim3 g(NCHUNK, BB);
    feat_part_kernel<<<g, 256>>>(x, mask);
    feat_reduce_kernel<<<BB*DD/256, 256>>>(out);
}

// round 2
// speedup vs baseline: 1.6720x; 1.6720x over previous
#include <cuda_runtime.h>
#include <math.h>

// Problem constants
#define BB 32
#define NN 4096
#define DD 512
#define CC 64
#define RTOT (BB*NN)          // 131072 rows
#define MT 32                 // rows per GEMM tile
#define NTILES (RTOT/MT)      // 4096
#define XP 516                // x_s pitch: 516 % 32 == 4 -> conflict-free A fragments
#define CHUNK 64              // rows per feature-partial block
#define NCHUNK (NN/CHUNK)     // 64

// Device scratch (allocation-free rule: __device__ globals)
__device__ float g_sw[(size_t)RTOT*CC];       // score * invnorm * valid, 32 MiB
__device__ int   g_counts[BB*CC];
__device__ int   g_index[BB];
__device__ float g_part[(size_t)BB*NCHUNK*DD]; // 4 MiB

// mask may be int64 (jax x64 on) or int32. Values in [1,4096]: if int64 LE,
// word 1 (high half of elem 0) is 0.
__device__ __forceinline__ int decode_mask(const int* mr, int b) {
    return (mr[1] == 0) ? mr[2*b] : mr[b];
}

__device__ __forceinline__ unsigned f2tf32_rna(float v) {
    unsigned u;
    asm("cvt.rna.tf32.f32 %0, %1;" : "=r"(u) : "f"(v));
    return u;
}

__device__ __forceinline__ void mma_tf32(float& d0, float& d1, float& d2, float& d3,
                                         unsigned a0, unsigned a1, unsigned a2, unsigned a3,
                                         unsigned b0, unsigned b1) {
    asm volatile("mma.sync.aligned.m16n8k8.row.col.f32.tf32.tf32.f32 "
                 "{%0,%1,%2,%3}, {%4,%5,%6,%7}, {%8,%9}, {%0,%1,%2,%3};"
                 : "+f"(d0), "+f"(d1), "+f"(d2), "+f"(d3)
                 : "r"(a0), "r"(a1), "r"(a2), "r"(a3), "r"(b0), "r"(b1));
}

__global__ void zero_counts_kernel() {
    int i = blockIdx.x*blockDim.x + threadIdx.x;
    if (i < BB*CC) g_counts[i] = 0;
}

__global__ __launch_bounds__(256, 1)
void main_kernel(const float* __restrict__ x, const int* __restrict__ maskr,
                 const float* __restrict__ anchors) {
    extern __shared__ float sm[];
    float*    a_s    = sm;                      // [DD][CC] anchors, tf32 bits, swizzled
    unsigned* a_su   = (unsigned*)a_s;
    float*    x_s    = a_s + DD*CC;             // [MT][XP] x tile fp32
    float*    dots_s = x_s + MT*XP;             // [MT][CC]
    float*    anorm_s= dots_s + MT*CC;          // [CC]
    float*    norm_s = anorm_s + CC;            // [MT]
    int*      mask_s = (int*)(norm_s + MT);     // [BB]

    const int tid  = threadIdx.x;
    const int lane = tid & 31, warp = tid >> 5;

    // ---- anchors -> smem as tf32 (rna), swizzled col' = (c + 8*(k&7)) & 63 ----
    for (int i = tid; i < CC*DD; i += 256) {
        int c = i >> 9;          // i / 512
        int k = i & (DD-1);
        int col = (c + 8*(k & 7)) & 63;
        a_su[k*CC + col] = f2tf32_rna(anchors[i]);
    }
    if (tid < BB) mask_s[tid] = decode_mask(maskr, tid);
    if (tid < CC) {
        float s = 0.f;
        const float* ar = anchors + (size_t)tid*DD;
        #pragma unroll 8
        for (int k = 0; k < DD; k++) { float v = ar[k]; s = fmaf(v, v, s); }
        anorm_s[tid] = s;
    }
    __syncthreads();

    // mma lane decomposition
    const int gid = lane >> 2, tig = lane & 3;
    const int mbase = (warp & 1) * 16;          // 2 m-slices of 16 rows
    const int nb0   = (warp >> 1) * 16;         // 4 n-slices of 16 cols
    const int col0  = (nb0 + gid + 8*tig) & 63; // B frag column (ntile 0)
    const int col1  = (col0 + 8) & 63;          // ntile 1

    // ---- tile loop with register prefetch of next valid tile ----
    int tile = blockIdx.x;
    while (tile < NTILES) {
        int b0i = (tile*MT) >> 12;
        if (((tile*MT) & (NN-1)) < mask_s[b0i]) break;
        tile += gridDim.x;
    }
    float4 v[16];
    if (tile < NTILES) {
        const float4* xg = (const float4*)(x + (size_t)tile*MT*DD);
        #pragma unroll
        for (int j = 0; j < 16; j++) v[j] = xg[tid + j*256];
    }

    while (tile < NTILES) {
        const int rowbase = tile*MT;
        const int b = rowbase >> 12;

        // store prefetched tile to smem
        #pragma unroll
        for (int j = 0; j < 16; j++) {
            int idx = tid + j*256;
            int r = idx >> 7, k4 = idx & 127;
            float* p = &x_s[r*XP + k4*4];
            p[0]=v[j].x; p[1]=v[j].y; p[2]=v[j].z; p[3]=v[j].w;
        }
        __syncthreads();

        // find + prefetch next valid tile (overlaps with mma below)
        int nt = tile + gridDim.x;
        while (nt < NTILES) {
            int nb = (nt*MT) >> 12;
            if (((nt*MT) & (NN-1)) < mask_s[nb]) break;
            nt += gridDim.x;
        }
        if (nt < NTILES) {
            const float4* xg = (const float4*)(x + (size_t)nt*MT*DD);
            #pragma unroll
            for (int j = 0; j < 16; j++) v[j] = xg[tid + j*256];
        }

        // ---- row norms (fp32, warp per row) ----
        for (int m = warp; m < MT; m += 8) {
            float s = 0.f;
            #pragma unroll 4
            for (int k = lane; k < DD; k += 32) { float q = x_s[m*XP + k]; s = fmaf(q, q, s); }
            #pragma unroll
            for (int o = 16; o; o >>= 1) s += __shfl_xor_sync(0xffffffffu, s, o);
            if (lane == 0) norm_s[m] = s;
        }

        // ---- tf32 mma: warp computes 16 rows x 16 cols ----
        float d00=0,d01=0,d02=0,d03=0, d10=0,d11=0,d12=0,d13=0;
        const float*    xa = x_s + (mbase + gid)*XP + tig;
        const unsigned* bp = a_su + tig*CC;
        #pragma unroll 8
        for (int k0 = 0; k0 < DD; k0 += 8) {
            unsigned a0 = __float_as_uint(xa[k0]);
            unsigned a1 = __float_as_uint(xa[8*XP + k0]);
            unsigned a2 = __float_as_uint(xa[k0 + 4]);
            unsigned a3 = __float_as_uint(xa[8*XP + k0 + 4]);
            const unsigned* bk = bp + k0*CC;
            unsigned b00 = bk[col0];
            unsigned b01 = bk[4*CC + (col0 ^ 32)];
            unsigned b10 = bk[col1];
            unsigned b11 = bk[4*CC + (col1 ^ 32)];
            mma_tf32(d00,d01,d02,d03, a0,a1,a2,a3, b00,b01);
            mma_tf32(d10,d11,d12,d13, a0,a1,a2,a3, b10,b11);
        }
        {
            const int r0 = mbase + gid, r1 = r0 + 8, cb = 2*tig;
            dots_s[r0*CC + nb0 + cb]     = d00;
            dots_s[r0*CC + nb0 + cb + 1] = d01;
            dots_s[r1*CC + nb0 + cb]     = d02;
            dots_s[r1*CC + nb0 + cb + 1] = d03;
            dots_s[r0*CC + nb0 + 8 + cb]     = d10;
            dots_s[r0*CC + nb0 + 8 + cb + 1] = d11;
            dots_s[r1*CC + nb0 + 8 + cb]     = d12;
            dots_s[r1*CC + nb0 + 8 + cb + 1] = d13;
        }
        __syncthreads();

        // ---- per-row epilogue: dist -> softmax(1/dist) -> store, argmax, counts ----
        for (int m = warp; m < MT; m += 8) {
            const int row = rowbase + m;
            const int n = row & (NN-1);
            const bool valid = n < mask_s[b];
            const float n2  = norm_s[m];
            const float inv = 1.f / fmaxf(sqrtf(n2), 1e-12f);
            const float sxn2 = n2 * inv * inv;
            const int cA = lane, cB = lane + 32;
            const float dA = dots_s[m*CC + cA], dB = dots_s[m*CC + cB];
            const float sqA = sxn2 + anorm_s[cA] - 2.f*dA*inv;
            const float sqB = sxn2 + anorm_s[cB] - 2.f*dB*inv;
            const float idA = 1.f / sqrtf(fmaxf(sqA, 0.f));
            const float idB = 1.f / sqrtf(fmaxf(sqB, 0.f));
            float mx = fmaxf(idA, idB);
            #pragma unroll
            for (int o = 16; o; o >>= 1) mx = fmaxf(mx, __shfl_xor_sync(0xffffffffu, mx, o));
            const float eA = expf(idA - mx), eB = expf(idB - mx);
            float ss = eA + eB;
            #pragma unroll
            for (int o = 16; o; o >>= 1) ss += __shfl_xor_sync(0xffffffffu, ss, o);
            const float rs = 1.f / ss;
            const size_t base = (size_t)row * CC;
            g_sw[base + cA] = valid ? eA*rs*inv : 0.f;
            g_sw[base + cB] = valid ? eB*rs*inv : 0.f;
            float bv; int bi;
            if (idB > idA) { bv = idB; bi = cB; } else { bv = idA; bi = cA; }
            #pragma unroll
            for (int o = 16; o; o >>= 1) {
                float ov = __shfl_xor_sync(0xffffffffu, bv, o);
                int   oi = __shfl_xor_sync(0xffffffffu, bi, o);
                if (ov > bv || (ov == bv && oi < bi)) { bv = ov; bi = oi; }
            }
            if (lane == 0 && valid) atomicAdd(&g_counts[b*CC + bi], 1);
        }
        __syncthreads();
        tile = nt;
    }
}

__global__ void index_kernel() {
    __shared__ int sv[CC], si[CC];
    const int b = blockIdx.x, c = threadIdx.x;
    sv[c] = g_counts[b*CC + c]; si[c] = c;
    __syncthreads();
    for (int o = 32; o; o >>= 1) {
        if (c < o) {
            if (sv[c+o] > sv[c] || (sv[c+o] == sv[c] && si[c+o] < si[c])) {
                sv[c] = sv[c+o]; si[c] = si[c+o];
            }
        }
        __syncthreads();
    }
    if (c == 0) g_index[b] = si[0];
}

__global__ __launch_bounds__(256)
void feat_part_kernel(const float* __restrict__ x, const int* __restrict__ maskr) {
    const int b = blockIdx.y, ch = blockIdx.x;
    const int tid = threadIdx.x;
    __shared__ float w_s[CHUNK];
    __shared__ int s_idx, s_nv;
    if (tid == 0) {
        s_idx = g_index[b];
        int nv = decode_mask(maskr, b) - ch*CHUNK;
        s_nv = nv < 0 ? 0 : (nv > CHUNK ? CHUNK : nv);
    }
    __syncthreads();
    const int nv = s_nv;
    float* gp = g_part + ((size_t)b*NCHUNK + ch)*DD;
    if (nv == 0) {
        ((float2*)gp)[tid] = make_float2(0.f, 0.f);
        return;
    }
    const int idx = s_idx;
    const int rowbase = b*NN + ch*CHUNK;
    if (tid < CHUNK) w_s[tid] = (tid < nv) ? g_sw[(size_t)(rowbase + tid)*CC + idx] : 0.f;
    __syncthreads();
    float ax = 0.f, ay = 0.f;
    const float2* xb = (const float2*)(x + (size_t)rowbase*DD);
    int r = 0;
    for (; r + 8 <= nv; r += 8) {
        float2 vv[8];
        #pragma unroll
        for (int u = 0; u < 8; u++) vv[u] = xb[(size_t)(r+u)*256 + tid];
        #pragma unroll
        for (int u = 0; u < 8; u++) {
            float w = w_s[r+u];
            ax = fmaf(vv[u].x, w, ax);
            ay = fmaf(vv[u].y, w, ay);
        }
    }
    for (; r < nv; r++) {
        float2 vv = xb[(size_t)r*256 + tid];
        float w = w_s[r];
        ax = fmaf(vv.x, w, ax);
        ay = fmaf(vv.y, w, ay);
    }
    ((float2*)gp)[tid] = make_float2(ax, ay);
}

__global__ void feat_reduce_kernel(float* __restrict__ out) {
    const int i = blockIdx.x*blockDim.x + threadIdx.x;  // BB*DD = 16384
    const int b = i >> 9, d = i & (DD-1);
    float s = 0.f;
    #pragma unroll 8
    for (int ch = 0; ch < NCHUNK; ch++) s += g_part[((size_t)b*NCHUNK + ch)*DD + d];
    out[i] = s;
}

extern "C" void kernel_launch(void* const* d_in, const int* in_sizes, int n_in,
                              void* d_out, int out_size) {
    const float* x       = (const float*)d_in[0];
    const int*   mask    = (const int*)d_in[1];
    const float* anchors = (const float*)d_in[2];
    float* out = (float*)d_out;

    const size_t smem = (size_t)(DD*CC + MT*XP + MT*CC + CC + MT)*sizeof(float)
                      + BB*sizeof(int);   // ~201 KB
    cudaFuncSetAttribute(main_kernel, cudaFuncAttributeMaxDynamicSharedMemorySize, (int)smem);

    zero_counts_kernel<<<8, 256>>>();
    main_kernel<<<152, 256, smem>>>(x, mask, anchors);
    index_kernel<<<BB, CC>>>();
    dim3 g(NCHUNK, BB);
    feat_part_kernel<<<g, 256>>>(x, mask);
    feat_reduce_kernel<<<BB*DD/256, 256>>>(out);
}

// round 3
// speedup vs baseline: 1.9759x; 1.1817x over previous
#include <cuda_runtime.h>
#include <math.h>

// Problem constants
#define BB 32
#define NN 4096
#define DD 512
#define CC 64
#define RTOT (BB*NN)          // 131072 rows
#define MT 32                 // rows per GEMM tile
#define NTILES (RTOT/MT)      // 4096
#define XP 516                // x_s pitch: 516 % 32 == 4 -> conflict-free A fragments
#define CHUNK 64              // rows per feature chunk
#define NCHUNK (NN/CHUNK)     // 64
#define NPART (NCHUNK*2)      // two half-chunk partials per chunk

// Device scratch (allocation-free rule: __device__ globals)
__device__ float g_sw[(size_t)RTOT*CC];          // score*invnorm*valid, 32 MiB
__device__ int   g_counts[BB*CC];
__device__ int   g_index[BB];
__device__ float g_part[(size_t)BB*NPART*DD];    // 8 MiB

// mask may be int64 (jax x64) or int32. Values in [1,4096]: if int64 LE,
// word 1 (high half of elem 0) is 0.
__device__ __forceinline__ int decode_mask(const int* mr, int b) {
    return (mr[1] == 0) ? mr[2*b] : mr[b];
}

__device__ __forceinline__ unsigned f2tf32_rna(float v) {
    unsigned u;
    asm("cvt.rna.tf32.f32 %0, %1;" : "=r"(u) : "f"(v));
    return u;
}

__device__ __forceinline__ void mma_tf32(float& d0, float& d1, float& d2, float& d3,
                                         unsigned a0, unsigned a1, unsigned a2, unsigned a3,
                                         unsigned b0, unsigned b1) {
    asm volatile("mma.sync.aligned.m16n8k8.row.col.f32.tf32.tf32.f32 "
                 "{%0,%1,%2,%3}, {%4,%5,%6,%7}, {%8,%9}, {%0,%1,%2,%3};"
                 : "+f"(d0), "+f"(d1), "+f"(d2), "+f"(d3)
                 : "r"(a0), "r"(a1), "r"(a2), "r"(a3), "r"(b0), "r"(b1));
}

__global__ void zero_counts_kernel() {
    int i = blockIdx.x*blockDim.x + threadIdx.x;
    if (i < BB*CC) g_counts[i] = 0;
}

__global__ __launch_bounds__(512, 1)
void main_kernel(const float* __restrict__ x, const int* __restrict__ maskr,
                 const float* __restrict__ anchors) {
    extern __shared__ float sm[];
    float*    a_s    = sm;                      // [DD][CC] anchors tf32, swizzled
    unsigned* a_su   = (unsigned*)a_s;
    float*    x_s    = a_s + DD*CC;             // [MT][XP]
    float*    dots_s = x_s + MT*XP;             // [2][MT][CC] k-split partials
    float*    anorm_s= dots_s + 2*MT*CC;        // [CC]
    float*    norm_s = anorm_s + CC;            // [MT]
    int*      mask_s = (int*)(norm_s + MT);     // [BB]

    const int tid  = threadIdx.x;
    const int lane = tid & 31, warp = tid >> 5;   // 16 warps

    // ---- anchors -> smem tf32 (rna), swizzled col' = (c + 8*(k&7)) & 63 ----
    for (int i = tid; i < CC*DD; i += 512) {
        int c = i >> 9;          // i / 512
        int k = i & (DD-1);
        int col = (c + 8*(k & 7)) & 63;
        a_su[k*CC + col] = f2tf32_rna(anchors[i]);
    }
    if (tid < BB) mask_s[tid] = decode_mask(maskr, tid);
    if (tid < CC) {
        float s = 0.f;
        const float* ar = anchors + (size_t)tid*DD;
        #pragma unroll 8
        for (int k = 0; k < DD; k++) { float v = ar[k]; s = fmaf(v, v, s); }
        anorm_s[tid] = s;
    }
    __syncthreads();

    // warp decomposition: mslice (2) x nslice (4) x khalf (2)
    const int gid = lane >> 2, tig = lane & 3;
    const int mbase = (warp & 1) * 16;
    const int nb0   = ((warp >> 1) & 3) * 16;
    const int kh    = warp >> 3;                 // 0/1: k offset kh*256
    const int col0  = (nb0 + gid + 8*tig) & 63;
    const int col1  = (col0 + 8) & 63;

    // load mapping: thread -> one row, 8 float4 slots
    const int lrow  = tid >> 4;                  // 0..31
    const int lslot = tid & 15;                  // float4 slot base

    // ---- find first valid tile, prefetch into registers ----
    int tile = blockIdx.x;
    while (tile < NTILES) {
        int bb = (tile*MT) >> 12;
        if (((tile*MT) & (NN-1)) < mask_s[bb]) break;
        tile += gridDim.x;
    }
    float4 v[8];
    if (tile < NTILES) {
        const float4* xg = (const float4*)(x + (size_t)tile*MT*DD) + lrow*128 + lslot;
        #pragma unroll
        for (int j = 0; j < 8; j++) v[j] = xg[16*j];
    }

    while (tile < NTILES) {
        const int rowbase = tile*MT;
        const int b = rowbase >> 12;

        // store tile to smem + row norm from registers
        float ns = 0.f;
        #pragma unroll
        for (int j = 0; j < 8; j++) {
            float4 q = v[j];
            *reinterpret_cast<float4*>(&x_s[lrow*XP + 4*(lslot + 16*j)]) = q;
            ns = fmaf(q.x,q.x, fmaf(q.y,q.y, fmaf(q.z,q.z, fmaf(q.w,q.w, ns))));
        }
        #pragma unroll
        for (int o = 8; o; o >>= 1) ns += __shfl_xor_sync(0xffffffffu, ns, o);
        if ((lane & 15) == 0) norm_s[lrow] = ns;
        __syncthreads();

        // find + prefetch next valid tile (overlaps with mma)
        int nt = tile + gridDim.x;
        while (nt < NTILES) {
            int nb = (nt*MT) >> 12;
            if (((nt*MT) & (NN-1)) < mask_s[nb]) break;
            nt += gridDim.x;
        }
        if (nt < NTILES) {
            const float4* xg = (const float4*)(x + (size_t)nt*MT*DD) + lrow*128 + lslot;
            #pragma unroll
            for (int j = 0; j < 8; j++) v[j] = xg[16*j];
        }

        // ---- tf32 mma: warp computes 16 rows x 16 cols over its k-half ----
        float d00=0,d01=0,d02=0,d03=0, d10=0,d11=0,d12=0,d13=0;
        const float*    xa = x_s + (mbase + gid)*XP + tig + kh*256;
        const unsigned* bp = a_su + (kh*256 + tig)*CC;
        #pragma unroll 8
        for (int k0 = 0; k0 < 256; k0 += 8) {
            unsigned a0 = __float_as_uint(xa[k0]);
            unsigned a1 = __float_as_uint(xa[8*XP + k0]);
            unsigned a2 = __float_as_uint(xa[k0 + 4]);
            unsigned a3 = __float_as_uint(xa[8*XP + k0 + 4]);
            const unsigned* bk = bp + k0*CC;
            unsigned b00 = bk[col0];
            unsigned b01 = bk[4*CC + (col0 ^ 32)];
            unsigned b10 = bk[col1];
            unsigned b11 = bk[4*CC + (col1 ^ 32)];
            mma_tf32(d00,d01,d02,d03, a0,a1,a2,a3, b00,b01);
            mma_tf32(d10,d11,d12,d13, a0,a1,a2,a3, b10,b11);
        }
        {
            float* dh = dots_s + kh*MT*CC;
            const int r0 = mbase + gid, r1 = r0 + 8, cb = 2*tig;
            dh[r0*CC + nb0 + cb]     = d00;
            dh[r0*CC + nb0 + cb + 1] = d01;
            dh[r1*CC + nb0 + cb]     = d02;
            dh[r1*CC + nb0 + cb + 1] = d03;
            dh[r0*CC + nb0 + 8 + cb]     = d10;
            dh[r0*CC + nb0 + 8 + cb + 1] = d11;
            dh[r1*CC + nb0 + 8 + cb]     = d12;
            dh[r1*CC + nb0 + 8 + cb + 1] = d13;
        }
        __syncthreads();

        // ---- epilogue: 2 rows per warp ----
        #pragma unroll
        for (int u = 0; u < 2; u++) {
            const int m = warp*2 + u;
            const int row = rowbase + m;
            const int n = row & (NN-1);
            const bool valid = n < mask_s[b];
            const float n2  = norm_s[m];
            const float inv = 1.f / fmaxf(sqrtf(n2), 1e-12f);
            const float sxn2 = n2 * inv * inv;
            const int cA = lane, cB = lane + 32;
            const float dA = dots_s[m*CC + cA] + dots_s[MT*CC + m*CC + cA];
            const float dB = dots_s[m*CC + cB] + dots_s[MT*CC + m*CC + cB];
            const float sqA = sxn2 + anorm_s[cA] - 2.f*dA*inv;
            const float sqB = sxn2 + anorm_s[cB] - 2.f*dB*inv;
            const float idA = rsqrtf(fmaxf(sqA, 1e-30f));
            const float idB = rsqrtf(fmaxf(sqB, 1e-30f));
            float mx = fmaxf(idA, idB);
            #pragma unroll
            for (int o = 16; o; o >>= 1) mx = fmaxf(mx, __shfl_xor_sync(0xffffffffu, mx, o));
            const float eA = __expf(idA - mx), eB = __expf(idB - mx);
            float ss = eA + eB;
            #pragma unroll
            for (int o = 16; o; o >>= 1) ss += __shfl_xor_sync(0xffffffffu, ss, o);
            const float rs = 1.f / ss;
            const size_t base = (size_t)row * CC;
            g_sw[base + cA] = valid ? eA*rs*inv : 0.f;
            g_sw[base + cB] = valid ? eB*rs*inv : 0.f;
            float bv; int bi;
            if (idB > idA) { bv = idB; bi = cB; } else { bv = idA; bi = cA; }
            #pragma unroll
            for (int o = 16; o; o >>= 1) {
                float ov = __shfl_xor_sync(0xffffffffu, bv, o);
                int   oi = __shfl_xor_sync(0xffffffffu, bi, o);
                if (ov > bv || (ov == bv && oi < bi)) { bv = ov; bi = oi; }
            }
            if (lane == 0 && valid) atomicAdd(&g_counts[b*CC + bi], 1);
        }
        __syncthreads();
        tile = nt;
    }
}

__global__ void index_kernel() {
    __shared__ int sv[CC], si[CC];
    const int b = blockIdx.x, c = threadIdx.x;
    sv[c] = g_counts[b*CC + c]; si[c] = c;
    __syncthreads();
    for (int o = 32; o; o >>= 1) {
        if (c < o) {
            if (sv[c+o] > sv[c] || (sv[c+o] == sv[c] && si[c+o] < si[c])) {
                sv[c] = sv[c+o]; si[c] = si[c+o];
            }
        }
        __syncthreads();
    }
    if (c == 0) g_index[b] = si[0];
}

// 256 threads: half = tid>>7 handles rows [half*32, half*32+32) of the chunk,
// col4 = tid&127 is this thread's float4 column. float4 loads, 8-deep batches.
__global__ __launch_bounds__(256)
void feat_part_kernel(const float* __restrict__ x, const int* __restrict__ maskr) {
    const int b = blockIdx.y, ch = blockIdx.x;
    const int tid = threadIdx.x;
    const int half = tid >> 7, col4 = tid & 127;
    __shared__ float w_s[CHUNK];
    __shared__ int s_idx, s_nv;
    if (tid == 0) {
        s_idx = g_index[b];
        int nv = decode_mask(maskr, b) - ch*CHUNK;
        s_nv = nv < 0 ? 0 : (nv > CHUNK ? CHUNK : nv);
    }
    __syncthreads();
    const int nv = s_nv;
    float4* gp = (float4*)(g_part + ((size_t)(b*NCHUNK + ch)*2 + half)*DD);
    if (nv == 0) {
        gp[col4] = make_float4(0.f, 0.f, 0.f, 0.f);
        return;
    }
    const int idx = s_idx;
    const int rowbase = b*NN + ch*CHUNK;
    if (tid < CHUNK) w_s[tid] = (tid < nv) ? g_sw[(size_t)(rowbase + tid)*CC + idx] : 0.f;
    __syncthreads();

    int cnt = nv - half*32;
    cnt = cnt < 0 ? 0 : (cnt > 32 ? 32 : cnt);
    const float4* xb = (const float4*)(x + (size_t)(rowbase + half*32)*DD) + col4;
    const float*  wb = w_s + half*32;
    float ax=0.f, ay=0.f, az=0.f, aw=0.f;
    int r = 0;
    for (; r + 8 <= cnt; r += 8) {
        float4 vv[8];
        #pragma unroll
        for (int u = 0; u < 8; u++) vv[u] = xb[(size_t)(r+u)*128];
        #pragma unroll
        for (int u = 0; u < 8; u++) {
            float w = wb[r+u];
            ax = fmaf(vv[u].x, w, ax); ay = fmaf(vv[u].y, w, ay);
            az = fmaf(vv[u].z, w, az); aw = fmaf(vv[u].w, w, aw);
        }
    }
    for (; r < cnt; r++) {
        float4 vv = xb[(size_t)r*128];
        float w = wb[r];
        ax = fmaf(vv.x, w, ax); ay = fmaf(vv.y, w, ay);
        az = fmaf(vv.z, w, az); aw = fmaf(vv.w, w, aw);
    }
    gp[col4] = make_float4(ax, ay, az, aw);
}

// sum NPART partials per (b, d4): 4096 float4 outputs
__global__ void feat_reduce_kernel(float* __restrict__ out) {
    const int i4 = blockIdx.x*blockDim.x + threadIdx.x;   // BB*DD/4 = 4096
    const int b = i4 >> 7, d4 = i4 & 127;
    const float4* gp = (const float4*)g_part + (size_t)b*NPART*128 + d4;
    float ax=0.f, ay=0.f, az=0.f, aw=0.f;
    #pragma unroll 8
    for (int ch = 0; ch < NPART; ch++) {
        float4 q = gp[(size_t)ch*128];
        ax += q.x; ay += q.y; az += q.z; aw += q.w;
    }
    ((float4*)out)[i4] = make_float4(ax, ay, az, aw);
}

extern "C" void kernel_launch(void* const* d_in, const int* in_sizes, int n_in,
                              void* d_out, int out_size) {
    const float* x       = (const float*)d_in[0];
    const int*   mask    = (const int*)d_in[1];
    const float* anchors = (const float*)d_in[2];
    float* out = (float*)d_out;

    const size_t smem = (size_t)(DD*CC + MT*XP + 2*MT*CC + CC + MT)*sizeof(float)
                      + BB*sizeof(int);   // ~209 KB
    cudaFuncSetAttribute(main_kernel, cudaFuncAttributeMaxDynamicSharedMemorySize, (int)smem);

    zero_counts_kernel<<<8, 256>>>();
    main_kernel<<<152, 512, smem>>>(x, mask, anchors);
    index_kernel<<<BB, CC>>>();
    dim3 g(NCHUNK, BB);
    feat_part_kernel<<<g, 256>>>(x, mask);
    feat_reduce_kernel<<<16, 256>>>(out);
}

// round 5
// speedup vs baseline: 2.7663x; 1.4001x over previous
#include <cuda_runtime.h>
#include <cuda_fp16.h>
#include <math.h>
#include <stdint.h>

// Problem constants
#define BB 32
#define NN 4096
#define DD 512
#define CC 64
#define RTOT (BB*NN)          // 131072 rows
#define MT 32                 // rows per GEMM tile
#define NTILES (RTOT/MT)      // 4096
#define XPH 520               // x_s pitch in halves: 520/2 = 260 ≡ 4 (mod 32) -> conflict-free
#define APH 520               // anchor pitch in halves (same property)
#define CHUNK 64              // rows per feature chunk
#define NCHUNK (NN/CHUNK)     // 64

// Device scratch (allocation-free rule: __device__ globals)
__device__ float g_sw[(size_t)RTOT*CC];        // score*invnorm*valid, 32 MiB
__device__ int   g_counts[BB*CC];
__device__ int   g_index[BB];
__device__ float g_part[(size_t)BB*NCHUNK*DD]; // 16 MiB

// mask may be int64 (jax x64) or int32. Values in [1,4096]: if int64 LE,
// word 1 (high half of elem 0) is 0.
__device__ __forceinline__ int decode_mask(const int* mr, int b) {
    return (mr[1] == 0) ? mr[2*b] : mr[b];
}

__device__ __forceinline__ void mma_f16(float& d0, float& d1, float& d2, float& d3,
                                        unsigned a0, unsigned a1, unsigned a2, unsigned a3,
                                        unsigned b0, unsigned b1) {
    asm volatile("mma.sync.aligned.m16n8k16.row.col.f32.f16.f16.f32 "
                 "{%0,%1,%2,%3}, {%4,%5,%6,%7}, {%8,%9}, {%0,%1,%2,%3};"
                 : "+f"(d0), "+f"(d1), "+f"(d2), "+f"(d3)
                 : "r"(a0), "r"(a1), "r"(a2), "r"(a3), "r"(b0), "r"(b1));
}

__global__ __launch_bounds__(512, 1)
void main_kernel(const float* __restrict__ x, const int* __restrict__ maskr,
                 const float* __restrict__ anchors) {
    extern __shared__ char smem[];
    __half*   a_h    = (__half*)smem;                    // [CC][APH] anchors fp16 (k-contig)
    __half*   x_h    = a_h + CC*APH;                     // [MT][XPH] x tile fp16
    float*    dots_s = (float*)(x_h + MT*XPH);           // [2][MT][CC] k-half partials
    float*    anorm_s= dots_s + 2*MT*CC;                 // [CC]
    float*    norm_s = anorm_s + CC;                     // [MT]
    int*      mask_s = (int*)(norm_s + MT);              // [BB]

    const int tid  = threadIdx.x;
    const int lane = tid & 31, warp = tid >> 5;           // 16 warps

    // ---- anchors -> smem fp16, [c][k] with pitch APH ----
    for (int i = tid; i < CC*DD; i += 512) {
        int c = i >> 9;          // i / 512
        int k = i & (DD-1);
        a_h[c*APH + k] = __float2half_rn(anchors[i]);
    }
    if (tid < BB) mask_s[tid] = decode_mask(maskr, tid);
    if (tid < CC) {
        float s = 0.f;
        const float* ar = anchors + (size_t)tid*DD;
        #pragma unroll 8
        for (int k = 0; k < DD; k++) { float q = ar[k]; s = fmaf(q, q, s); }
        anorm_s[tid] = s;
    }
    __syncthreads();

    // warp decomposition: mslice (2) x nslice (4) x khalf (2)
    const int gid = lane >> 2, tig = lane & 3;
    const int mbase = (warp & 1) * 16;
    const int nb0   = ((warp >> 1) & 3) * 16;
    const int kh    = warp >> 3;                 // 0/1: k offset kh*256

    // load mapping: thread -> one row, 8 float4 slots
    const int lrow  = tid >> 4;                  // 0..31
    const int lslot = tid & 15;

    // ---- find first valid tile, prefetch into registers ----
    int tile = blockIdx.x;
    while (tile < NTILES) {
        int bb = (tile*MT) >> 12;
        if (((tile*MT) & (NN-1)) < mask_s[bb]) break;
        tile += gridDim.x;
    }
    float4 v[8];
    if (tile < NTILES) {
        const float4* xg = (const float4*)(x + (size_t)tile*MT*DD) + lrow*128 + lslot;
        #pragma unroll
        for (int j = 0; j < 8; j++) v[j] = xg[16*j];
    }

    while (tile < NTILES) {
        const int rowbase = tile*MT;
        const int b = rowbase >> 12;

        // store tile to smem (fp16) + row norm from fp32 registers
        float ns = 0.f;
        #pragma unroll
        for (int j = 0; j < 8; j++) {
            float4 q = v[j];
            __half2 h01 = __floats2half2_rn(q.x, q.y);
            __half2 h23 = __floats2half2_rn(q.z, q.w);
            uint2 st;
            st.x = *(unsigned*)&h01;
            st.y = *(unsigned*)&h23;
            *(uint2*)((char*)x_h + lrow*(XPH*2) + (lslot + 16*j)*8) = st;
            ns = fmaf(q.x,q.x, fmaf(q.y,q.y, fmaf(q.z,q.z, fmaf(q.w,q.w, ns))));
        }
        #pragma unroll
        for (int o = 8; o; o >>= 1) ns += __shfl_xor_sync(0xffffffffu, ns, o);
        if ((lane & 15) == 0) norm_s[lrow] = ns;
        __syncthreads();

        // find + prefetch next valid tile (overlaps with mma)
        int nt = tile + gridDim.x;
        while (nt < NTILES) {
            int nb = (nt*MT) >> 12;
            if (((nt*MT) & (NN-1)) < mask_s[nb]) break;
            nt += gridDim.x;
        }
        if (nt < NTILES) {
            const float4* xg = (const float4*)(x + (size_t)nt*MT*DD) + lrow*128 + lslot;
            #pragma unroll
            for (int j = 0; j < 8; j++) v[j] = xg[16*j];
        }

        // ---- fp16 mma: warp computes 16 rows x 16 cols over its k-half ----
        float d00=0,d01=0,d02=0,d03=0, d10=0,d11=0,d12=0,d13=0;
        const __half* xa = x_h + (mbase + gid)*XPH + kh*256 + 2*tig;
        const __half* b0p = a_h + (nb0 + gid)*APH     + kh*256 + 2*tig;
        const __half* b1p = a_h + (nb0 + gid + 8)*APH + kh*256 + 2*tig;
        #pragma unroll
        for (int k0 = 0; k0 < 256; k0 += 16) {
            unsigned a0 = *(const unsigned*)(xa + k0);
            unsigned a1 = *(const unsigned*)(xa + 8*XPH + k0);
            unsigned a2 = *(const unsigned*)(xa + k0 + 8);
            unsigned a3 = *(const unsigned*)(xa + 8*XPH + k0 + 8);
            unsigned b00 = *(const unsigned*)(b0p + k0);
            unsigned b01 = *(const unsigned*)(b0p + k0 + 8);
            unsigned b10 = *(const unsigned*)(b1p + k0);
            unsigned b11 = *(const unsigned*)(b1p + k0 + 8);
            mma_f16(d00,d01,d02,d03, a0,a1,a2,a3, b00,b01);
            mma_f16(d10,d11,d12,d13, a0,a1,a2,a3, b10,b11);
        }
        {
            float* dh = dots_s + kh*MT*CC;
            const int r0 = mbase + gid, r1 = r0 + 8, cb = 2*tig;
            dh[r0*CC + nb0 + cb]     = d00;
            dh[r0*CC + nb0 + cb + 1] = d01;
            dh[r1*CC + nb0 + cb]     = d02;
            dh[r1*CC + nb0 + cb + 1] = d03;
            dh[r0*CC + nb0 + 8 + cb]     = d10;
            dh[r0*CC + nb0 + 8 + cb + 1] = d11;
            dh[r1*CC + nb0 + 8 + cb]     = d12;
            dh[r1*CC + nb0 + 8 + cb + 1] = d13;
        }
        __syncthreads();

        // ---- epilogue: 2 rows per warp ----
        #pragma unroll
        for (int u = 0; u < 2; u++) {
            const int m = warp*2 + u;
            const int row = rowbase + m;
            const int n = row & (NN-1);
            const bool valid = n < mask_s[b];
            const float n2  = norm_s[m];
            const float inv = 1.f / fmaxf(sqrtf(n2), 1e-12f);
            const float sxn2 = n2 * inv * inv;
            const int cA = lane, cB = lane + 32;
            const float dA = dots_s[m*CC + cA] + dots_s[MT*CC + m*CC + cA];
            const float dB = dots_s[m*CC + cB] + dots_s[MT*CC + m*CC + cB];
            const float sqA = sxn2 + anorm_s[cA] - 2.f*dA*inv;
            const float sqB = sxn2 + anorm_s[cB] - 2.f*dB*inv;
            const float idA = rsqrtf(fmaxf(sqA, 1e-30f));
            const float idB = rsqrtf(fmaxf(sqB, 1e-30f));
            float mx = fmaxf(idA, idB);
            #pragma unroll
            for (int o = 16; o; o >>= 1) mx = fmaxf(mx, __shfl_xor_sync(0xffffffffu, mx, o));
            const float eA = __expf(idA - mx), eB = __expf(idB - mx);
            float ss = eA + eB;
            #pragma unroll
            for (int o = 16; o; o >>= 1) ss += __shfl_xor_sync(0xffffffffu, ss, o);
            const float rs = 1.f / ss;
            const size_t base = (size_t)row * CC;
            g_sw[base + cA] = valid ? eA*rs*inv : 0.f;
            g_sw[base + cB] = valid ? eB*rs*inv : 0.f;
            float bv; int bi;
            if (idB > idA) { bv = idB; bi = cB; } else { bv = idA; bi = cA; }
            #pragma unroll
            for (int o = 16; o; o >>= 1) {
                float ov = __shfl_xor_sync(0xffffffffu, bv, o);
                int   oi = __shfl_xor_sync(0xffffffffu, bi, o);
                if (ov > bv || (ov == bv && oi < bi)) { bv = ov; bi = oi; }
            }
            if (lane == 0 && valid) atomicAdd(&g_counts[b*CC + bi], 1);
        }
        __syncthreads();
        tile = nt;
    }
}

// argmax of counts per batch; also resets counts for the next graph replay
__global__ void index_kernel() {
    __shared__ int sv[CC], si[CC];
    const int b = blockIdx.x, c = threadIdx.x;
    sv[c] = g_counts[b*CC + c]; si[c] = c;
    g_counts[b*CC + c] = 0;
    __syncthreads();
    for (int o = 32; o; o >>= 1) {
        if (c < o) {
            if (sv[c+o] > sv[c] || (sv[c+o] == sv[c] && si[c+o] < si[c])) {
                sv[c] = sv[c+o]; si[c] = si[c+o];
            }
        }
        __syncthreads();
    }
    if (c == 0) g_index[b] = si[0];
}

__global__ __launch_bounds__(256)
void feat_part_kernel(const float* __restrict__ x, const int* __restrict__ maskr) {
    const int b = blockIdx.y, ch = blockIdx.x;
    const int tid = threadIdx.x;
    __shared__ float w_s[CHUNK];
    __shared__ int s_idx, s_nv;
    if (tid == 0) {
        s_idx = g_index[b];
        int nv = decode_mask(maskr, b) - ch*CHUNK;
        s_nv = nv < 0 ? 0 : (nv > CHUNK ? CHUNK : nv);
    }
    __syncthreads();
    const int nv = s_nv;
    float* gp = g_part + ((size_t)b*NCHUNK + ch)*DD;
    if (nv == 0) {
        ((float2*)gp)[tid] = make_float2(0.f, 0.f);
        return;
    }
    const int idx = s_idx;
    const int rowbase = b*NN + ch*CHUNK;
    if (tid < CHUNK) w_s[tid] = (tid < nv) ? g_sw[(size_t)(rowbase + tid)*CC + idx] : 0.f;
    __syncthreads();
    float ax = 0.f, ay = 0.f;
    const float2* xb = (const float2*)(x + (size_t)rowbase*DD);
    int r = 0;
    for (; r + 8 <= nv; r += 8) {
        float2 vv[8];
        #pragma unroll
        for (int u = 0; u < 8; u++) vv[u] = xb[(size_t)(r+u)*256 + tid];
        #pragma unroll
        for (int u = 0; u < 8; u++) {
            float w = w_s[r+u];
            ax = fmaf(vv[u].x, w, ax);
            ay = fmaf(vv[u].y, w, ay);
        }
    }
    for (; r < nv; r++) {
        float2 vv = xb[(size_t)r*256 + tid];
        float w = w_s[r];
        ax = fmaf(vv.x, w, ax);
        ay = fmaf(vv.y, w, ay);
    }
    ((float2*)gp)[tid] = make_float2(ax, ay);
}

__global__ void feat_reduce_kernel(float* __restrict__ out) {
    const int i = blockIdx.x*blockDim.x + threadIdx.x;  // BB*DD = 16384
    const int b = i >> 9, d = i & (DD-1);
    float s = 0.f;
    #pragma unroll 8
    for (int ch = 0; ch < NCHUNK; ch++) s += g_part[((size_t)b*NCHUNK + ch)*DD + d];
    out[i] = s;
}

extern "C" void kernel_launch(void* const* d_in, const int* in_sizes, int n_in,
                              void* d_out, int out_size) {
    const float* x       = (const float*)d_in[0];
    const int*   mask    = (const int*)d_in[1];
    const float* anchors = (const float*)d_in[2];
    float* out = (float*)d_out;

    const size_t smem = (size_t)(CC*APH + MT*XPH)*sizeof(__half)
                      + (size_t)(2*MT*CC + CC + MT)*sizeof(float)
                      + BB*sizeof(int);   // ~117 KB
    cudaFuncSetAttribute(main_kernel, cudaFuncAttributeMaxDynamicSharedMemorySize, (int)smem);

    main_kernel<<<152, 512, smem>>>(x, mask, anchors);
    index_kernel<<<BB, CC>>>();
    dim3 g(NCHUNK, BB);
    feat_part_kernel<<<g, 256>>>(x, mask);
    feat_reduce_kernel<<<BB*DD/256, 256>>>(out);
}